// round 3
// baseline (speedup 1.0000x reference)
#include <cuda_runtime.h>
#include <math.h>

// ---------------------------------------------------------------------------
// Problem constants (from reference): N=50000, E=800000, IN=256, C=64, H=4
// ---------------------------------------------------------------------------
#define NMAX   50000
#define EMAX   800000
#define E2MAX  (EMAX + NMAX)
#define HC     256          // H*C
#define CCH    64           // C
#define NEG_SLOPE 0.2f

// ---------------------------------------------------------------------------
// Scratch (static __device__ globals; no runtime allocation)
// ---------------------------------------------------------------------------
__device__ __align__(256) float g_xl[(size_t)NMAX * HC];
__device__ __align__(256) float g_xr[(size_t)NMAX * HC];
__device__ __align__(256) float g_h1[(size_t)NMAX * CCH];
__device__ __align__(256) float g_h2[(size_t)NMAX * CCH];
__device__ __align__(256) int   g_cnt[NMAX];
__device__ __align__(256) float g_sumattr[NMAX];
__device__ __align__(256) float g_loopattr[NMAX];
__device__ __align__(256) int   g_off[NMAX + 2];
__device__ __align__(256) int   g_cursor[NMAX];
__device__ __align__(256) int   g_csr_src[E2MAX];
__device__ __align__(256) float g_csr_attr[E2MAX];
__device__ int g_is64;   // 1 if edge_index buffer holds int64, 0 if int32

// ---------------------------------------------------------------------------
// Index decode helpers (dtype decided at runtime by probe kernel)
// ---------------------------------------------------------------------------
__device__ __forceinline__ int load_idx(const void* ei, int is64, size_t pos) {
    if (is64) return (int)((const long long*)ei)[pos];
    return ((const int*)ei)[pos];
}

// Probe: if data is int64 with values < 2^31, every odd 32-bit word is 0.
__global__ void detect_kernel(const int* ei32, int e) {
    if (threadIdx.x != 0 || blockIdx.x != 0) return;
    int nz = 0;
    int lim = (e < 64) ? e : 64;
    for (int i = 0; i < lim; ++i) nz |= ei32[2 * i + 1];
    g_is64 = (nz == 0) ? 1 : 0;
}

// ---------------------------------------------------------------------------
// init: zero per-node counters
// ---------------------------------------------------------------------------
__global__ void init_kernel(int n) {
    int i = blockIdx.x * blockDim.x + threadIdx.x;
    if (i < n) { g_cnt[i] = 0; g_sumattr[i] = 0.f; }
}

// ---------------------------------------------------------------------------
// CSR build: count incoming edges + sum edge_attr per dst
// ---------------------------------------------------------------------------
__global__ void count_kernel(const void* __restrict__ ei,
                             const float* __restrict__ eattr, int e, int n) {
    int i = blockIdx.x * blockDim.x + threadIdx.x;
    if (i >= e) return;
    int is64 = g_is64;
    int d = load_idx(ei, is64, (size_t)e + i);
    if ((unsigned)d >= (unsigned)n) return;   // defensive: never trap
    atomicAdd(&g_cnt[d], 1);
    atomicAdd(&g_sumattr[d], eattr[i]);
}

__global__ void loopattr_kernel(int n) {
    int i = blockIdx.x * blockDim.x + threadIdx.x;
    if (i >= n) return;
    int c = g_cnt[i];
    g_loopattr[i] = g_sumattr[i] / (float)(c > 1 ? c : 1);
}

// Exclusive scan of (cnt[i]+1) -> offsets; single block of 1024 threads.
__global__ void scan_kernel(int n) {
    __shared__ int sm[1024];
    __shared__ int s_carry;
    int tid = threadIdx.x;
    if (tid == 0) s_carry = 0;
    __syncthreads();
    for (int base = 0; base < n; base += 1024) {
        int i = base + tid;
        int v = (i < n) ? (g_cnt[i] + 1) : 0;
        sm[tid] = v;
        __syncthreads();
        for (int d = 1; d < 1024; d <<= 1) {
            int t = (tid >= d) ? sm[tid - d] : 0;
            __syncthreads();
            sm[tid] += t;
            __syncthreads();
        }
        int incl = sm[tid];
        int excl = incl - v + s_carry;
        if (i < n) { g_off[i] = excl; g_cursor[i] = excl; }
        __syncthreads();
        if (tid == 1023) s_carry += incl;
        __syncthreads();
    }
    if (tid == 0) g_off[n] = s_carry;
}

__global__ void fill_kernel(const void* __restrict__ ei,
                            const float* __restrict__ eattr, int e, int n) {
    int i = blockIdx.x * blockDim.x + threadIdx.x;
    if (i >= e) return;
    int is64 = g_is64;
    int s = load_idx(ei, is64, (size_t)i);
    int d = load_idx(ei, is64, (size_t)e + i);
    if ((unsigned)d >= (unsigned)n || (unsigned)s >= (unsigned)n) return;
    int pos = atomicAdd(&g_cursor[d], 1);
    g_csr_src[pos]  = s;
    g_csr_attr[pos] = eattr[i];
}

__global__ void fill_loop_kernel(int n) {
    int i = blockIdx.x * blockDim.x + threadIdx.x;
    if (i >= n) return;
    int pos = atomicAdd(&g_cursor[i], 1);
    g_csr_src[pos]  = i;
    g_csr_attr[pos] = g_loopattr[i];
}

// ---------------------------------------------------------------------------
// Tiled fp32 GEMM with bias: C[M,256] = A[M,K] @ W[K,256] + b
// BM=64, BN=64, BK=16, 256 threads, 4x4 per thread.
// ---------------------------------------------------------------------------
#define BM 64
#define BN 64
#define BK 16

__global__ void gemm_bias_kernel(const float* __restrict__ A,
                                 const float* __restrict__ W,
                                 const float* __restrict__ b,
                                 float* __restrict__ C,
                                 int M, int K) {
    __shared__ __align__(16) float As[BK][BM];
    __shared__ __align__(16) float Bs[BK][BN];
    const int NCOLS = HC;  // 256
    int n0 = blockIdx.x * BN;
    int m0 = blockIdx.y * BM;
    int tid = threadIdx.x;
    int tx = tid & 15, ty = tid >> 4;

    float acc[4][4] = {};

    for (int k0 = 0; k0 < K; k0 += BK) {
        // A tile: 64 rows x 16 cols, one float4 per thread
        {
            int row = tid >> 2;
            int c4  = (tid & 3) * 4;
            int m   = m0 + row;
            float4 v = make_float4(0.f, 0.f, 0.f, 0.f);
            if (m < M) v = *(const float4*)(A + (size_t)m * K + k0 + c4);
            As[c4 + 0][row] = v.x;
            As[c4 + 1][row] = v.y;
            As[c4 + 2][row] = v.z;
            As[c4 + 3][row] = v.w;
        }
        // W tile: 16 rows x 64 cols, one float4 per thread
        {
            int row = tid >> 4;
            int c4  = (tid & 15) * 4;
            *(float4*)&Bs[row][c4] =
                *(const float4*)(W + (size_t)(k0 + row) * NCOLS + n0 + c4);
        }
        __syncthreads();
        #pragma unroll
        for (int k = 0; k < BK; ++k) {
            float4 a4 = *(const float4*)&As[k][ty * 4];
            float4 b4 = *(const float4*)&Bs[k][tx * 4];
            float av[4] = {a4.x, a4.y, a4.z, a4.w};
            float bv[4] = {b4.x, b4.y, b4.z, b4.w};
            #pragma unroll
            for (int i = 0; i < 4; ++i)
                #pragma unroll
                for (int j = 0; j < 4; ++j)
                    acc[i][j] += av[i] * bv[j];
        }
        __syncthreads();
    }

    float4 bv = *(const float4*)(b + n0 + tx * 4);
    float bb[4] = {bv.x, bv.y, bv.z, bv.w};
    #pragma unroll
    for (int i = 0; i < 4; ++i) {
        int m = m0 + ty * 4 + i;
        if (m < M) {
            float4 o;
            o.x = acc[i][0] + bb[0];
            o.y = acc[i][1] + bb[1];
            o.z = acc[i][2] + bb[2];
            o.w = acc[i][3] + bb[3];
            *(float4*)(C + (size_t)m * NCOLS + n0 + tx * 4) = o;
        }
    }
}

// ---------------------------------------------------------------------------
// Fused GATv2 edge phase: one warp per destination node.
// lane -> head = lane>>3, owns 8 channels (lane&7)*8.. of that head.
// Pass 1: score max per head. Pass 2: den = sum exp, acc = sum exp*xl[src].
// out[n,c] = mean_h( acc_h[c] / (den_h + 1e-16) ) + bias[c]  (+ PReLU on last)
// ---------------------------------------------------------------------------
__global__ void gat_edge_kernel(const float* __restrict__ xl,
                                const float* __restrict__ xr,
                                const float* __restrict__ We,
                                const float* __restrict__ att,
                                const float* __restrict__ bias,
                                const float* __restrict__ prelu_w,
                                float* __restrict__ out,
                                int n, int use_prelu) {
    int warp = (blockIdx.x * blockDim.x + threadIdx.x) >> 5;
    if (warp >= n) return;
    int lane = threadIdx.x & 31;
    int sub  = lane & 7;
    int base = (lane >> 3) * CCH + sub * 8;

    float we[8], at[8], xrv[8];
    {
        float4 a = *(const float4*)(We + base);
        float4 b = *(const float4*)(We + base + 4);
        we[0]=a.x; we[1]=a.y; we[2]=a.z; we[3]=a.w;
        we[4]=b.x; we[5]=b.y; we[6]=b.z; we[7]=b.w;
        a = *(const float4*)(att + base);
        b = *(const float4*)(att + base + 4);
        at[0]=a.x; at[1]=a.y; at[2]=a.z; at[3]=a.w;
        at[4]=b.x; at[5]=b.y; at[6]=b.z; at[7]=b.w;
        const float* xp = xr + (size_t)warp * HC + base;
        a = *(const float4*)xp;
        b = *(const float4*)(xp + 4);
        xrv[0]=a.x; xrv[1]=a.y; xrv[2]=a.z; xrv[3]=a.w;
        xrv[4]=b.x; xrv[5]=b.y; xrv[6]=b.z; xrv[7]=b.w;
    }

    int p0 = g_off[warp], p1 = g_off[warp + 1];

    // Pass 1: per-head max score
    float mx = -1e30f;
    for (int p = p0; p < p1; ++p) {
        int s   = g_csr_src[p];
        float a = g_csr_attr[p];
        const float* xp = xl + (size_t)s * HC + base;
        float4 v0 = *(const float4*)xp;
        float4 v1 = *(const float4*)(xp + 4);
        float xv[8] = {v0.x, v0.y, v0.z, v0.w, v1.x, v1.y, v1.z, v1.w};
        float sc = 0.f;
        #pragma unroll
        for (int j = 0; j < 8; ++j) {
            float m = xv[j] + xrv[j] + a * we[j];
            m = (m >= 0.f) ? m : NEG_SLOPE * m;
            sc += m * at[j];
        }
        sc += __shfl_xor_sync(0xffffffffu, sc, 1);
        sc += __shfl_xor_sync(0xffffffffu, sc, 2);
        sc += __shfl_xor_sync(0xffffffffu, sc, 4);
        mx = fmaxf(mx, sc);
    }

    // Pass 2: denominator + weighted accumulation
    float den = 0.f;
    float acc[8] = {};
    for (int p = p0; p < p1; ++p) {
        int s   = g_csr_src[p];
        float a = g_csr_attr[p];
        const float* xp = xl + (size_t)s * HC + base;
        float4 v0 = *(const float4*)xp;
        float4 v1 = *(const float4*)(xp + 4);
        float xv[8] = {v0.x, v0.y, v0.z, v0.w, v1.x, v1.y, v1.z, v1.w};
        float sc = 0.f;
        #pragma unroll
        for (int j = 0; j < 8; ++j) {
            float m = xv[j] + xrv[j] + a * we[j];
            m = (m >= 0.f) ? m : NEG_SLOPE * m;
            sc += m * at[j];
        }
        sc += __shfl_xor_sync(0xffffffffu, sc, 1);
        sc += __shfl_xor_sync(0xffffffffu, sc, 2);
        sc += __shfl_xor_sync(0xffffffffu, sc, 4);
        float ex = __expf(sc - mx);
        den += ex;
        #pragma unroll
        for (int j = 0; j < 8; ++j) acc[j] += ex * xv[j];
    }

    float invd = 1.f / (den + 1e-16f);
    float res[8];
    #pragma unroll
    for (int j = 0; j < 8; ++j) {
        float v = acc[j] * invd;                    // per-head normalized
        v += __shfl_xor_sync(0xffffffffu, v, 8);    // sum across heads
        v += __shfl_xor_sync(0xffffffffu, v, 16);
        res[j] = v * 0.25f;                         // mean over H=4
    }
    if (lane < 8) {
        #pragma unroll
        for (int j = 0; j < 8; ++j) {
            int c = sub * 8 + j;
            float o = res[j] + bias[c];
            if (use_prelu) o = (o >= 0.f) ? o : prelu_w[c] * o;
            out[(size_t)warp * CCH + c] = o;
        }
    }
}

// ---------------------------------------------------------------------------
// Host launch
// ---------------------------------------------------------------------------
extern "C" void kernel_launch(void* const* d_in, const int* in_sizes, int n_in,
                              void* d_out, int out_size) {
    const float* x     = (const float*)d_in[0];
    const void*  ei    = d_in[1];                 // int32 OR int64 — probed on device
    const float* eattr = (const float*)d_in[2];

    const float* Wl[3]   = {(const float*)d_in[3],  (const float*)d_in[10], (const float*)d_in[17]};
    const float* bl[3]   = {(const float*)d_in[4],  (const float*)d_in[11], (const float*)d_in[18]};
    const float* Wr[3]   = {(const float*)d_in[5],  (const float*)d_in[12], (const float*)d_in[19]};
    const float* br[3]   = {(const float*)d_in[6],  (const float*)d_in[13], (const float*)d_in[20]};
    const float* We[3]   = {(const float*)d_in[7],  (const float*)d_in[14], (const float*)d_in[21]};
    const float* att[3]  = {(const float*)d_in[8],  (const float*)d_in[15], (const float*)d_in[22]};
    const float* bias[3] = {(const float*)d_in[9],  (const float*)d_in[16], (const float*)d_in[23]};
    const float* prelu_w = (const float*)d_in[24];

    int n = in_sizes[0] / 256;  // 50000
    int e = in_sizes[2];        // 800000 (edge_attr element count, dtype-independent)

    float *xl, *xr, *h1, *h2;
    cudaGetSymbolAddress((void**)&xl, g_xl);
    cudaGetSymbolAddress((void**)&xr, g_xr);
    cudaGetSymbolAddress((void**)&h1, g_h1);
    cudaGetSymbolAddress((void**)&h2, g_h2);

    // --- Probe edge_index dtype, then build CSR (dst-sorted, + self loops) ---
    detect_kernel<<<1, 32>>>((const int*)ei, e);
    init_kernel<<<(n + 255) / 256, 256>>>(n);
    count_kernel<<<(e + 255) / 256, 256>>>(ei, eattr, e, n);
    loopattr_kernel<<<(n + 255) / 256, 256>>>(n);
    scan_kernel<<<1, 1024>>>(n);
    fill_kernel<<<(e + 255) / 256, 256>>>(ei, eattr, e, n);
    fill_loop_kernel<<<(n + 255) / 256, 256>>>(n);

    dim3 gemm_grid(HC / BN, (n + BM - 1) / BM);
    int edge_blocks = (n * 32 + 255) / 256;

    // --- Layer 1 (K=256) ---
    gemm_bias_kernel<<<gemm_grid, 256>>>(x, Wl[0], bl[0], xl, n, 256);
    gemm_bias_kernel<<<gemm_grid, 256>>>(x, Wr[0], br[0], xr, n, 256);
    gat_edge_kernel<<<edge_blocks, 256>>>(xl, xr, We[0], att[0], bias[0],
                                          prelu_w, h1, n, 0);
    // --- Layer 2 (K=64) ---
    gemm_bias_kernel<<<gemm_grid, 256>>>(h1, Wl[1], bl[1], xl, n, 64);
    gemm_bias_kernel<<<gemm_grid, 256>>>(h1, Wr[1], br[1], xr, n, 64);
    gat_edge_kernel<<<edge_blocks, 256>>>(xl, xr, We[1], att[1], bias[1],
                                          prelu_w, h2, n, 0);
    // --- Layer 3 (K=64) + PReLU fused ---
    gemm_bias_kernel<<<gemm_grid, 256>>>(h2, Wl[2], bl[2], xl, n, 64);
    gemm_bias_kernel<<<gemm_grid, 256>>>(h2, Wr[2], br[2], xr, n, 64);
    gat_edge_kernel<<<edge_blocks, 256>>>(xl, xr, We[2], att[2], bias[2],
                                          prelu_w, (float*)d_out, n, 1);
}

// round 4
// speedup vs baseline: 1.2672x; 1.2672x over previous
#include <cuda_runtime.h>
#include <math.h>

// ---------------------------------------------------------------------------
// Problem constants: N=50000, E=800000, IN=256, C=64, H=4
// ---------------------------------------------------------------------------
#define NMAX   50000
#define EMAX   800000
#define E2MAX  (EMAX + NMAX)
#define HC     256          // H*C
#define CCH    64           // C
#define NEG_SLOPE 0.2f

// ---------------------------------------------------------------------------
// Scratch (static __device__ globals)
// ---------------------------------------------------------------------------
__device__ __align__(256) float g_xl[(size_t)NMAX * HC];
__device__ __align__(256) float g_xr[(size_t)NMAX * HC];
__device__ __align__(256) float g_h1[(size_t)NMAX * CCH];
__device__ __align__(256) float g_h2[(size_t)NMAX * CCH];
__device__ __align__(256) int   g_cnt[NMAX];
__device__ __align__(256) float g_sumattr[NMAX];
__device__ __align__(256) float g_loopattr[NMAX];
__device__ __align__(256) int   g_off[NMAX + 2];
__device__ __align__(256) int   g_cursor[NMAX];
__device__ __align__(256) int   g_csr_src[E2MAX];
__device__ __align__(256) float g_csr_attr[E2MAX];
__device__ int g_is64;

// ---------------------------------------------------------------------------
// Index decode (edge_index may be materialized as int32 or int64)
// ---------------------------------------------------------------------------
__device__ __forceinline__ int load_idx(const void* ei, int is64, size_t pos) {
    if (is64) return (int)((const long long*)ei)[pos];
    return ((const int*)ei)[pos];
}

__global__ void detect_kernel(const int* ei32, int e) {
    if (threadIdx.x != 0 || blockIdx.x != 0) return;
    int nz = 0;
    int lim = (e < 64) ? e : 64;
    for (int i = 0; i < lim; ++i) nz |= ei32[2 * i + 1];
    g_is64 = (nz == 0) ? 1 : 0;
}

__global__ void init_kernel(int n) {
    int i = blockIdx.x * blockDim.x + threadIdx.x;
    if (i < n) { g_cnt[i] = 0; g_sumattr[i] = 0.f; }
}

__global__ void count_kernel(const void* __restrict__ ei,
                             const float* __restrict__ eattr, int e, int n) {
    int i = blockIdx.x * blockDim.x + threadIdx.x;
    if (i >= e) return;
    int is64 = g_is64;
    int d = load_idx(ei, is64, (size_t)e + i);
    if ((unsigned)d >= (unsigned)n) return;
    atomicAdd(&g_cnt[d], 1);
    atomicAdd(&g_sumattr[d], eattr[i]);
}

__global__ void loopattr_kernel(int n) {
    int i = blockIdx.x * blockDim.x + threadIdx.x;
    if (i >= n) return;
    int c = g_cnt[i];
    g_loopattr[i] = g_sumattr[i] / (float)(c > 1 ? c : 1);
}

__global__ void scan_kernel(int n) {
    __shared__ int sm[1024];
    __shared__ int s_carry;
    int tid = threadIdx.x;
    if (tid == 0) s_carry = 0;
    __syncthreads();
    for (int base = 0; base < n; base += 1024) {
        int i = base + tid;
        int v = (i < n) ? (g_cnt[i] + 1) : 0;
        sm[tid] = v;
        __syncthreads();
        for (int d = 1; d < 1024; d <<= 1) {
            int t = (tid >= d) ? sm[tid - d] : 0;
            __syncthreads();
            sm[tid] += t;
            __syncthreads();
        }
        int incl = sm[tid];
        int excl = incl - v + s_carry;
        if (i < n) { g_off[i] = excl; g_cursor[i] = excl; }
        __syncthreads();
        if (tid == 1023) s_carry += incl;
        __syncthreads();
    }
    if (tid == 0) g_off[n] = s_carry;
}

__global__ void fill_kernel(const void* __restrict__ ei,
                            const float* __restrict__ eattr, int e, int n) {
    int i = blockIdx.x * blockDim.x + threadIdx.x;
    if (i >= e) return;
    int is64 = g_is64;
    int s = load_idx(ei, is64, (size_t)i);
    int d = load_idx(ei, is64, (size_t)e + i);
    if ((unsigned)d >= (unsigned)n || (unsigned)s >= (unsigned)n) return;
    int pos = atomicAdd(&g_cursor[d], 1);
    g_csr_src[pos]  = s;
    g_csr_attr[pos] = eattr[i];
}

__global__ void fill_loop_kernel(int n) {
    int i = blockIdx.x * blockDim.x + threadIdx.x;
    if (i >= n) return;
    int pos = atomicAdd(&g_cursor[i], 1);
    g_csr_src[pos]  = i;
    g_csr_attr[pos] = g_loopattr[i];
}

// ---------------------------------------------------------------------------
// Dual GEMM, 128x128x16 tile, 256 threads, 8x8 micro-tile, reg prefetch.
// One launch computes BOTH xl = A@Wl + bl and xr = A@Wr + br.
// grid.x in [0,4): x<2 -> Wl tile cols x*128; x>=2 -> Wr tile cols (x-2)*128.
// ---------------------------------------------------------------------------
#define GBM 128
#define GBN 128
#define GBK 16

__global__ __launch_bounds__(256, 2)
void gemm_dual_kernel(const float* __restrict__ A,
                      const float* __restrict__ Wl, const float* __restrict__ bl,
                      const float* __restrict__ Wr, const float* __restrict__ br,
                      float* __restrict__ Cl, float* __restrict__ Cr,
                      int M, int K) {
    __shared__ __align__(16) float As[GBK][GBM];
    __shared__ __align__(16) float Bs[GBK][GBN];

    int bx = blockIdx.x;
    const float* W;
    const float* b;
    float* C;
    int n0;
    if (bx < 2) { W = Wl; b = bl; C = Cl; n0 = bx * GBN; }
    else        { W = Wr; b = br; C = Cr; n0 = (bx - 2) * GBN; }
    int m0 = blockIdx.y * GBM;

    int tid = threadIdx.x;
    int tx = tid & 15;          // 0..15 -> 8 output cols each
    int ty = tid >> 4;          // 0..15 -> 8 output rows each

    // A-load mapping: 2 float4 per thread (rows r, r+64; cols c4..c4+3)
    int ar = tid >> 2;          // 0..63
    int ac4 = (tid & 3) * 4;    // 0,4,8,12
    // B-load mapping: 2 float4 per thread (rows br_, br_+8; col bc4)
    int brow = tid >> 5;        // 0..7
    int bc4 = (tid & 31) * 4;   // 0..124

    float acc[8][8] = {};
    float4 avp[2], bvp[2];

    int ntiles = K / GBK;

    // Preload tile 0
    {
        int m1 = m0 + ar, m2 = m0 + ar + 64;
        avp[0] = (m1 < M) ? *(const float4*)(A + (size_t)m1 * K + ac4)
                          : make_float4(0.f, 0.f, 0.f, 0.f);
        avp[1] = (m2 < M) ? *(const float4*)(A + (size_t)m2 * K + ac4)
                          : make_float4(0.f, 0.f, 0.f, 0.f);
        bvp[0] = *(const float4*)(W + (size_t)brow * HC + n0 + bc4);
        bvp[1] = *(const float4*)(W + (size_t)(brow + 8) * HC + n0 + bc4);
    }

    for (int t = 0; t < ntiles; ++t) {
        // store prefetched -> smem
        As[ac4 + 0][ar] = avp[0].x; As[ac4 + 1][ar] = avp[0].y;
        As[ac4 + 2][ar] = avp[0].z; As[ac4 + 3][ar] = avp[0].w;
        As[ac4 + 0][ar + 64] = avp[1].x; As[ac4 + 1][ar + 64] = avp[1].y;
        As[ac4 + 2][ar + 64] = avp[1].z; As[ac4 + 3][ar + 64] = avp[1].w;
        *(float4*)&Bs[brow][bc4]     = bvp[0];
        *(float4*)&Bs[brow + 8][bc4] = bvp[1];
        __syncthreads();

        // prefetch next tile
        if (t + 1 < ntiles) {
            int k0 = (t + 1) * GBK;
            int m1 = m0 + ar, m2 = m0 + ar + 64;
            avp[0] = (m1 < M) ? *(const float4*)(A + (size_t)m1 * K + k0 + ac4)
                              : make_float4(0.f, 0.f, 0.f, 0.f);
            avp[1] = (m2 < M) ? *(const float4*)(A + (size_t)m2 * K + k0 + ac4)
                              : make_float4(0.f, 0.f, 0.f, 0.f);
            bvp[0] = *(const float4*)(W + (size_t)(k0 + brow) * HC + n0 + bc4);
            bvp[1] = *(const float4*)(W + (size_t)(k0 + brow + 8) * HC + n0 + bc4);
        }

        #pragma unroll
        for (int k = 0; k < GBK; ++k) {
            float4 a0 = *(const float4*)&As[k][ty * 8];
            float4 a1 = *(const float4*)&As[k][ty * 8 + 4];
            float4 b0 = *(const float4*)&Bs[k][tx * 8];
            float4 b1 = *(const float4*)&Bs[k][tx * 8 + 4];
            float av[8] = {a0.x, a0.y, a0.z, a0.w, a1.x, a1.y, a1.z, a1.w};
            float bv[8] = {b0.x, b0.y, b0.z, b0.w, b1.x, b1.y, b1.z, b1.w};
            #pragma unroll
            for (int i = 0; i < 8; ++i)
                #pragma unroll
                for (int j = 0; j < 8; ++j)
                    acc[i][j] += av[i] * bv[j];
        }
        __syncthreads();
    }

    // epilogue: bias + store
    float4 bb0 = *(const float4*)(b + n0 + tx * 8);
    float4 bb1 = *(const float4*)(b + n0 + tx * 8 + 4);
    #pragma unroll
    for (int i = 0; i < 8; ++i) {
        int m = m0 + ty * 8 + i;
        if (m < M) {
            float4 o0, o1;
            o0.x = acc[i][0] + bb0.x; o0.y = acc[i][1] + bb0.y;
            o0.z = acc[i][2] + bb0.z; o0.w = acc[i][3] + bb0.w;
            o1.x = acc[i][4] + bb1.x; o1.y = acc[i][5] + bb1.y;
            o1.z = acc[i][6] + bb1.z; o1.w = acc[i][7] + bb1.w;
            *(float4*)(C + (size_t)m * HC + n0 + tx * 8)     = o0;
            *(float4*)(C + (size_t)m * HC + n0 + tx * 8 + 4) = o1;
        }
    }
}

// ---------------------------------------------------------------------------
// Fused GATv2 edge phase — SINGLE PASS online softmax.
// One warp per destination node. lane -> head = lane>>3, 8 channels each.
// ---------------------------------------------------------------------------
__global__ void gat_edge_kernel(const float* __restrict__ xl,
                                const float* __restrict__ xr,
                                const float* __restrict__ We,
                                const float* __restrict__ att,
                                const float* __restrict__ bias,
                                const float* __restrict__ prelu_w,
                                float* __restrict__ out,
                                int n, int use_prelu) {
    int warp = (blockIdx.x * blockDim.x + threadIdx.x) >> 5;
    if (warp >= n) return;
    int lane = threadIdx.x & 31;
    int sub  = lane & 7;
    int base = (lane >> 3) * CCH + sub * 8;

    float we[8], at[8], xrv[8];
    {
        float4 a = *(const float4*)(We + base);
        float4 b = *(const float4*)(We + base + 4);
        we[0]=a.x; we[1]=a.y; we[2]=a.z; we[3]=a.w;
        we[4]=b.x; we[5]=b.y; we[6]=b.z; we[7]=b.w;
        a = *(const float4*)(att + base);
        b = *(const float4*)(att + base + 4);
        at[0]=a.x; at[1]=a.y; at[2]=a.z; at[3]=a.w;
        at[4]=b.x; at[5]=b.y; at[6]=b.z; at[7]=b.w;
        const float* xp = xr + (size_t)warp * HC + base;
        a = *(const float4*)xp;
        b = *(const float4*)(xp + 4);
        xrv[0]=a.x; xrv[1]=a.y; xrv[2]=a.z; xrv[3]=a.w;
        xrv[4]=b.x; xrv[5]=b.y; xrv[6]=b.z; xrv[7]=b.w;
    }

    int p0 = g_off[warp], p1 = g_off[warp + 1];

    // Online softmax: running max m, denominator den, accumulator acc[8]
    float mrun = -1e30f;
    float den = 0.f;
    float acc[8] = {};

    for (int p = p0; p < p1; ++p) {
        int s   = g_csr_src[p];
        float a = g_csr_attr[p];
        const float* xp = xl + (size_t)s * HC + base;
        float4 v0 = *(const float4*)xp;
        float4 v1 = *(const float4*)(xp + 4);
        float xv[8] = {v0.x, v0.y, v0.z, v0.w, v1.x, v1.y, v1.z, v1.w};
        float sc = 0.f;
        #pragma unroll
        for (int j = 0; j < 8; ++j) {
            float m = xv[j] + xrv[j] + a * we[j];
            m = (m >= 0.f) ? m : NEG_SLOPE * m;
            sc += m * at[j];
        }
        sc += __shfl_xor_sync(0xffffffffu, sc, 1);
        sc += __shfl_xor_sync(0xffffffffu, sc, 2);
        sc += __shfl_xor_sync(0xffffffffu, sc, 4);

        float mnew = fmaxf(mrun, sc);
        float corr = __expf(mrun - mnew);   // =0 on first edge, 1 if no new max
        float ex   = __expf(sc - mnew);
        den = den * corr + ex;
        #pragma unroll
        for (int j = 0; j < 8; ++j)
            acc[j] = acc[j] * corr + ex * xv[j];
        mrun = mnew;
    }

    float invd = 1.f / (den + 1e-16f);
    float res[8];
    #pragma unroll
    for (int j = 0; j < 8; ++j) {
        float v = acc[j] * invd;                    // per-head normalized
        v += __shfl_xor_sync(0xffffffffu, v, 8);    // sum over heads
        v += __shfl_xor_sync(0xffffffffu, v, 16);
        res[j] = v * 0.25f;                         // mean over H=4
    }
    if (lane < 8) {
        #pragma unroll
        for (int j = 0; j < 8; ++j) {
            int c = sub * 8 + j;
            float o = res[j] + bias[c];
            if (use_prelu) o = (o >= 0.f) ? o : prelu_w[c] * o;
            out[(size_t)warp * CCH + c] = o;
        }
    }
}

// ---------------------------------------------------------------------------
// Host launch
// ---------------------------------------------------------------------------
extern "C" void kernel_launch(void* const* d_in, const int* in_sizes, int n_in,
                              void* d_out, int out_size) {
    const float* x     = (const float*)d_in[0];
    const void*  ei    = d_in[1];
    const float* eattr = (const float*)d_in[2];

    const float* Wl[3]   = {(const float*)d_in[3],  (const float*)d_in[10], (const float*)d_in[17]};
    const float* bl[3]   = {(const float*)d_in[4],  (const float*)d_in[11], (const float*)d_in[18]};
    const float* Wr[3]   = {(const float*)d_in[5],  (const float*)d_in[12], (const float*)d_in[19]};
    const float* br[3]   = {(const float*)d_in[6],  (const float*)d_in[13], (const float*)d_in[20]};
    const float* We[3]   = {(const float*)d_in[7],  (const float*)d_in[14], (const float*)d_in[21]};
    const float* att[3]  = {(const float*)d_in[8],  (const float*)d_in[15], (const float*)d_in[22]};
    const float* bias[3] = {(const float*)d_in[9],  (const float*)d_in[16], (const float*)d_in[23]};
    const float* prelu_w = (const float*)d_in[24];

    int n = in_sizes[0] / 256;  // 50000
    int e = in_sizes[2];        // 800000

    float *xl, *xr, *h1, *h2;
    cudaGetSymbolAddress((void**)&xl, g_xl);
    cudaGetSymbolAddress((void**)&xr, g_xr);
    cudaGetSymbolAddress((void**)&h1, g_h1);
    cudaGetSymbolAddress((void**)&h2, g_h2);

    // --- Probe dtype + build CSR ---
    detect_kernel<<<1, 32>>>((const int*)ei, e);
    init_kernel<<<(n + 255) / 256, 256>>>(n);
    count_kernel<<<(e + 255) / 256, 256>>>(ei, eattr, e, n);
    loopattr_kernel<<<(n + 255) / 256, 256>>>(n);
    scan_kernel<<<1, 1024>>>(n);
    fill_kernel<<<(e + 255) / 256, 256>>>(ei, eattr, e, n);
    fill_loop_kernel<<<(n + 255) / 256, 256>>>(n);

    dim3 ggrid(4, (n + GBM - 1) / GBM);
    int edge_blocks = (n * 32 + 255) / 256;

    // --- Layer 1 (K=256) ---
    gemm_dual_kernel<<<ggrid, 256>>>(x, Wl[0], bl[0], Wr[0], br[0], xl, xr, n, 256);
    gat_edge_kernel<<<edge_blocks, 256>>>(xl, xr, We[0], att[0], bias[0],
                                          prelu_w, h1, n, 0);
    // --- Layer 2 (K=64) ---
    gemm_dual_kernel<<<ggrid, 256>>>(h1, Wl[1], bl[1], Wr[1], br[1], xl, xr, n, 64);
    gat_edge_kernel<<<edge_blocks, 256>>>(xl, xr, We[1], att[1], bias[1],
                                          prelu_w, h2, n, 0);
    // --- Layer 3 (K=64) + PReLU ---
    gemm_dual_kernel<<<ggrid, 256>>>(h2, Wl[2], bl[2], Wr[2], br[2], xl, xr, n, 64);
    gat_edge_kernel<<<edge_blocks, 256>>>(xl, xr, We[2], att[2], bias[2],
                                          prelu_w, (float*)d_out, n, 1);
}

// round 6
// speedup vs baseline: 1.5918x; 1.2561x over previous
#include <cuda_runtime.h>
#include <cuda_bf16.h>
#include <math.h>
#include <stdint.h>

// ---------------------------------------------------------------------------
// Problem constants: N=50000, E=800000, IN=256, C=64, H=4
// ---------------------------------------------------------------------------
#define NMAX   50000
#define EMAX   800000
#define E2MAX  (EMAX + NMAX)
#define HC     256          // H*C
#define CCH    64           // C
#define NEG_SLOPE 0.2f

// ---------------------------------------------------------------------------
// Scratch
// ---------------------------------------------------------------------------
__device__ __align__(256) float g_xl[(size_t)NMAX * HC];
__device__ __align__(256) float g_xr[(size_t)NMAX * HC];
__device__ __align__(256) float g_h1[(size_t)NMAX * CCH];
__device__ __align__(256) float g_h2[(size_t)NMAX * CCH];
__device__ __align__(256) __nv_bfloat16 g_ah[(size_t)NMAX * HC];
__device__ __align__(256) __nv_bfloat16 g_al[(size_t)NMAX * HC];
__device__ __align__(256) __nv_bfloat16 g_bhl[256 * 256];
__device__ __align__(256) __nv_bfloat16 g_bll[256 * 256];
__device__ __align__(256) __nv_bfloat16 g_bhr[256 * 256];
__device__ __align__(256) __nv_bfloat16 g_blr[256 * 256];
__device__ __align__(256) int   g_cnt[NMAX];
__device__ __align__(256) float g_sumattr[NMAX];
__device__ __align__(256) float g_loopattr[NMAX];
__device__ __align__(256) int   g_off[NMAX + 2];
__device__ __align__(256) int   g_cursor[NMAX];
__device__ __align__(256) int   g_csr_src[E2MAX];
__device__ __align__(256) float g_csr_attr[E2MAX];
__device__ int g_is64;

// ---------------------------------------------------------------------------
// edge_index dtype probe + CSR build
// ---------------------------------------------------------------------------
__device__ __forceinline__ int load_idx(const void* ei, int is64, size_t pos) {
    if (is64) return (int)((const long long*)ei)[pos];
    return ((const int*)ei)[pos];
}
__global__ void detect_kernel(const int* ei32, int e) {
    if (threadIdx.x != 0 || blockIdx.x != 0) return;
    int nz = 0;
    int lim = (e < 64) ? e : 64;
    for (int i = 0; i < lim; ++i) nz |= ei32[2 * i + 1];
    g_is64 = (nz == 0) ? 1 : 0;
}
__global__ void init_kernel(int n) {
    int i = blockIdx.x * blockDim.x + threadIdx.x;
    if (i < n) { g_cnt[i] = 0; g_sumattr[i] = 0.f; }
}
__global__ void count_kernel(const void* __restrict__ ei,
                             const float* __restrict__ eattr, int e, int n) {
    int i = blockIdx.x * blockDim.x + threadIdx.x;
    if (i >= e) return;
    int is64 = g_is64;
    int d = load_idx(ei, is64, (size_t)e + i);
    if ((unsigned)d >= (unsigned)n) return;
    atomicAdd(&g_cnt[d], 1);
    atomicAdd(&g_sumattr[d], eattr[i]);
}
__global__ void loopattr_kernel(int n) {
    int i = blockIdx.x * blockDim.x + threadIdx.x;
    if (i >= n) return;
    int c = g_cnt[i];
    g_loopattr[i] = g_sumattr[i] / (float)(c > 1 ? c : 1);
}
__global__ void scan_kernel(int n) {
    __shared__ int sm[1024];
    __shared__ int s_carry;
    int tid = threadIdx.x;
    if (tid == 0) s_carry = 0;
    __syncthreads();
    for (int base = 0; base < n; base += 1024) {
        int i = base + tid;
        int v = (i < n) ? (g_cnt[i] + 1) : 0;
        sm[tid] = v;
        __syncthreads();
        for (int d = 1; d < 1024; d <<= 1) {
            int t = (tid >= d) ? sm[tid - d] : 0;
            __syncthreads();
            sm[tid] += t;
            __syncthreads();
        }
        int incl = sm[tid];
        int excl = incl - v + s_carry;
        if (i < n) { g_off[i] = excl; g_cursor[i] = excl; }
        __syncthreads();
        if (tid == 1023) s_carry += incl;
        __syncthreads();
    }
    if (tid == 0) g_off[n] = s_carry;
}
__global__ void fill_kernel(const void* __restrict__ ei,
                            const float* __restrict__ eattr, int e, int n) {
    int i = blockIdx.x * blockDim.x + threadIdx.x;
    if (i >= e) return;
    int is64 = g_is64;
    int s = load_idx(ei, is64, (size_t)i);
    int d = load_idx(ei, is64, (size_t)e + i);
    if ((unsigned)d >= (unsigned)n || (unsigned)s >= (unsigned)n) return;
    int pos = atomicAdd(&g_cursor[d], 1);
    g_csr_src[pos]  = s;
    g_csr_attr[pos] = eattr[i];
}
__global__ void fill_loop_kernel(int n) {
    int i = blockIdx.x * blockDim.x + threadIdx.x;
    if (i >= n) return;
    int pos = atomicAdd(&g_cursor[i], 1);
    g_csr_src[pos]  = i;
    g_csr_attr[pos] = g_loopattr[i];
}

// ---------------------------------------------------------------------------
// fp32 -> bf16 hi/lo split (activations) and transposed hi/lo weights
// ---------------------------------------------------------------------------
__global__ void conv_a_kernel(const float* __restrict__ A,
                              __nv_bfloat16* __restrict__ Ah,
                              __nv_bfloat16* __restrict__ Al, int total) {
    int i = blockIdx.x * blockDim.x + threadIdx.x;
    if (i >= total) return;
    float v = A[i];
    __nv_bfloat16 h = __float2bfloat16(v);
    float r = v - __bfloat162float(h);
    Ah[i] = h;
    Al[i] = __float2bfloat16(r);
}
// W [K,256] row-major -> Bt [256,K] (K-major rows), hi/lo split
__global__ void conv_w_kernel(const float* __restrict__ W,
                              __nv_bfloat16* __restrict__ Bh,
                              __nv_bfloat16* __restrict__ Bl, int K) {
    int i = blockIdx.x * blockDim.x + threadIdx.x;
    if (i >= 256 * K) return;
    int nrow = i / K;
    int k = i - nrow * K;
    float v = W[(size_t)k * 256 + nrow];
    __nv_bfloat16 h = __float2bfloat16(v);
    float r = v - __bfloat162float(h);
    Bh[(size_t)nrow * K + k] = h;
    Bl[(size_t)nrow * K + k] = __float2bfloat16(r);
}

// ---------------------------------------------------------------------------
// HMMA GEMM (base-ISA mma.sync, bf16 3-split):
//   C[M,256] = A[M,K] @ W[K,256] + bias
// CTA tile 128(M) x 128(N), 8 warps (4m x 2n), warp tile 32x64.
// K staged through SMEM in chunks of 64, padded rows (72 bf16) for
// conflict-free fragment loads. blockIdx.y: 0 -> (Bh0,C0), 1 -> (Bh1,C1).
// blockIdx.z: N-half (n0 = z*128).
// ---------------------------------------------------------------------------
#define KC 64
#define PADW 36                       // padded row stride in 32-bit words (72 bf16)
#define ROWB (PADW * 4)               // padded row stride in bytes (144)
#define SM_AH 0
#define SM_AL (128 * ROWB)            // 18432
#define SM_BH (2 * 128 * ROWB)        // 36864
#define SM_BL (3 * 128 * ROWB)        // 55296
#define GEMM_SMEM (4 * 128 * ROWB)    // 73728

__device__ __forceinline__ void mma_bf16(float* c, const uint32_t* a,
                                         uint32_t b0, uint32_t b1) {
    asm volatile(
        "mma.sync.aligned.m16n8k16.row.col.f32.bf16.bf16.f32 "
        "{%0,%1,%2,%3}, {%4,%5,%6,%7}, {%8,%9}, {%0,%1,%2,%3};"
        : "+f"(c[0]), "+f"(c[1]), "+f"(c[2]), "+f"(c[3])
        : "r"(a[0]), "r"(a[1]), "r"(a[2]), "r"(a[3]), "r"(b0), "r"(b1));
}

__global__ __launch_bounds__(256)
void gemm_mma_kernel(const __nv_bfloat16* __restrict__ Ah,
                     const __nv_bfloat16* __restrict__ Al,
                     const __nv_bfloat16* __restrict__ Bh0,
                     const __nv_bfloat16* __restrict__ Bl0,
                     const float* __restrict__ bias0, float* __restrict__ C0,
                     const __nv_bfloat16* __restrict__ Bh1,
                     const __nv_bfloat16* __restrict__ Bl1,
                     const float* __restrict__ bias1, float* __restrict__ C1,
                     int M, int K) {
    extern __shared__ char dsm[];

    const __nv_bfloat16* Bh = blockIdx.y ? Bh1 : Bh0;
    const __nv_bfloat16* Bl = blockIdx.y ? Bl1 : Bl0;
    const float* bias = blockIdx.y ? bias1 : bias0;
    float* C = blockIdx.y ? C1 : C0;
    int m0 = blockIdx.x * 128;
    int n0 = blockIdx.z * 128;

    int tid = threadIdx.x;
    int wid = tid >> 5, lane = tid & 31;
    int warpM = wid & 3, warpN = wid >> 2;
    int r = lane >> 2, q = lane & 3;

    const uint32_t* AHw = (const uint32_t*)(dsm + SM_AH);
    const uint32_t* ALw = (const uint32_t*)(dsm + SM_AL);
    const uint32_t* BHw = (const uint32_t*)(dsm + SM_BH);
    const uint32_t* BLw = (const uint32_t*)(dsm + SM_BL);

    float acc[2][8][4] = {};

    // loader mapping: 256 threads -> 128 rows x 2 segments of 64B
    int lrow = tid >> 1;
    int lseg = tid & 1;

    int nchunks = K / KC;
    for (int t = 0; t < nchunks; ++t) {
        int k0 = t * KC;
        // ---- stage chunk into SMEM ----
        {
            int m = m0 + lrow;
            bool v = m < M;
            size_t ga = (size_t)m * K + k0 + lseg * 32;
            const uint4* sa_h = (const uint4*)(Ah + ga);
            const uint4* sa_l = (const uint4*)(Al + ga);
            size_t gb = (size_t)(n0 + lrow) * K + k0 + lseg * 32;
            const uint4* sb_h = (const uint4*)(Bh + gb);
            const uint4* sb_l = (const uint4*)(Bl + gb);
            uint32_t doff = lrow * ROWB + lseg * 64;
            uint4* da_h = (uint4*)(dsm + SM_AH + doff);
            uint4* da_l = (uint4*)(dsm + SM_AL + doff);
            uint4* db_h = (uint4*)(dsm + SM_BH + doff);
            uint4* db_l = (uint4*)(dsm + SM_BL + doff);
            uint4 z = make_uint4(0, 0, 0, 0);
            #pragma unroll
            for (int j = 0; j < 4; ++j) {
                da_h[j] = v ? sa_h[j] : z;
                da_l[j] = v ? sa_l[j] : z;
                db_h[j] = sb_h[j];
                db_l[j] = sb_l[j];
            }
        }
        __syncthreads();

        // ---- compute on chunk: 4 ksteps of 16 ----
        #pragma unroll
        for (int ks = 0; ks < KC / 16; ++ks) {
            int kw = ks * 8;
            uint32_t ah[2][4], al[2][4];
            #pragma unroll
            for (int mi = 0; mi < 2; ++mi) {
                int rb  = (warpM * 32 + mi * 16 + r) * PADW + kw + q;
                int rb8 = rb + 8 * PADW;
                ah[mi][0] = AHw[rb];     ah[mi][1] = AHw[rb8];
                ah[mi][2] = AHw[rb + 4]; ah[mi][3] = AHw[rb8 + 4];
                al[mi][0] = ALw[rb];     al[mi][1] = ALw[rb8];
                al[mi][2] = ALw[rb + 4]; al[mi][3] = ALw[rb8 + 4];
            }
            #pragma unroll
            for (int ni = 0; ni < 8; ++ni) {
                int nb = (warpN * 64 + ni * 8 + r) * PADW + kw + q;
                uint32_t bh0 = BHw[nb], bh1 = BHw[nb + 4];
                uint32_t bl0 = BLw[nb], bl1 = BLw[nb + 4];
                #pragma unroll
                for (int mi = 0; mi < 2; ++mi) {
                    mma_bf16(acc[mi][ni], ah[mi], bh0, bh1);
                    mma_bf16(acc[mi][ni], ah[mi], bl0, bl1);
                    mma_bf16(acc[mi][ni], al[mi], bh0, bh1);
                }
            }
        }
        __syncthreads();
    }

    // ---- epilogue: bias + store ----
    #pragma unroll
    for (int ni = 0; ni < 8; ++ni) {
        int gn = n0 + warpN * 64 + ni * 8 + q * 2;
        float bx = bias[gn], by = bias[gn + 1];
        #pragma unroll
        for (int mi = 0; mi < 2; ++mi) {
            int gm = m0 + warpM * 32 + mi * 16 + r;
            if (gm < M) {
                float2 o0 = make_float2(acc[mi][ni][0] + bx, acc[mi][ni][1] + by);
                *(float2*)(C + (size_t)gm * 256 + gn) = o0;
            }
            if (gm + 8 < M) {
                float2 o1 = make_float2(acc[mi][ni][2] + bx, acc[mi][ni][3] + by);
                *(float2*)(C + (size_t)(gm + 8) * 256 + gn) = o1;
            }
        }
    }
}

// ---------------------------------------------------------------------------
// Fused GATv2 edge phase — single-pass online softmax, one warp per dst node.
// ---------------------------------------------------------------------------
__global__ void gat_edge_kernel(const float* __restrict__ xl,
                                const float* __restrict__ xr,
                                const float* __restrict__ We,
                                const float* __restrict__ att,
                                const float* __restrict__ bias,
                                const float* __restrict__ prelu_w,
                                float* __restrict__ out,
                                int n, int use_prelu) {
    int warp = (blockIdx.x * blockDim.x + threadIdx.x) >> 5;
    if (warp >= n) return;
    int lane = threadIdx.x & 31;
    int sub  = lane & 7;
    int base = (lane >> 3) * CCH + sub * 8;

    float we[8], at[8], xrv[8];
    {
        float4 a = *(const float4*)(We + base);
        float4 b = *(const float4*)(We + base + 4);
        we[0]=a.x; we[1]=a.y; we[2]=a.z; we[3]=a.w;
        we[4]=b.x; we[5]=b.y; we[6]=b.z; we[7]=b.w;
        a = *(const float4*)(att + base);
        b = *(const float4*)(att + base + 4);
        at[0]=a.x; at[1]=a.y; at[2]=a.z; at[3]=a.w;
        at[4]=b.x; at[5]=b.y; at[6]=b.z; at[7]=b.w;
        const float* xp = xr + (size_t)warp * HC + base;
        a = *(const float4*)xp;
        b = *(const float4*)(xp + 4);
        xrv[0]=a.x; xrv[1]=a.y; xrv[2]=a.z; xrv[3]=a.w;
        xrv[4]=b.x; xrv[5]=b.y; xrv[6]=b.z; xrv[7]=b.w;
    }

    int p0 = g_off[warp], p1 = g_off[warp + 1];

    float mrun = -1e30f;
    float den = 0.f;
    float acc[8] = {};

    for (int p = p0; p < p1; ++p) {
        int s   = g_csr_src[p];
        float a = g_csr_attr[p];
        const float* xp = xl + (size_t)s * HC + base;
        float4 v0 = *(const float4*)xp;
        float4 v1 = *(const float4*)(xp + 4);
        float xv[8] = {v0.x, v0.y, v0.z, v0.w, v1.x, v1.y, v1.z, v1.w};
        float sc = 0.f;
        #pragma unroll
        for (int j = 0; j < 8; ++j) {
            float m = xv[j] + xrv[j] + a * we[j];
            m = (m >= 0.f) ? m : NEG_SLOPE * m;
            sc += m * at[j];
        }
        sc += __shfl_xor_sync(0xffffffffu, sc, 1);
        sc += __shfl_xor_sync(0xffffffffu, sc, 2);
        sc += __shfl_xor_sync(0xffffffffu, sc, 4);

        float mnew = fmaxf(mrun, sc);
        float corr = __expf(mrun - mnew);
        float ex   = __expf(sc - mnew);
        den = den * corr + ex;
        #pragma unroll
        for (int j = 0; j < 8; ++j)
            acc[j] = acc[j] * corr + ex * xv[j];
        mrun = mnew;
    }

    float invd = 1.f / (den + 1e-16f);
    float res[8];
    #pragma unroll
    for (int j = 0; j < 8; ++j) {
        float v = acc[j] * invd;
        v += __shfl_xor_sync(0xffffffffu, v, 8);
        v += __shfl_xor_sync(0xffffffffu, v, 16);
        res[j] = v * 0.25f;
    }
    if (lane < 8) {
        #pragma unroll
        for (int j = 0; j < 8; ++j) {
            int c = sub * 8 + j;
            float o = res[j] + bias[c];
            if (use_prelu) o = (o >= 0.f) ? o : prelu_w[c] * o;
            out[(size_t)warp * CCH + c] = o;
        }
    }
}

// ---------------------------------------------------------------------------
// Host launch
// ---------------------------------------------------------------------------
extern "C" void kernel_launch(void* const* d_in, const int* in_sizes, int n_in,
                              void* d_out, int out_size) {
    const float* x     = (const float*)d_in[0];
    const void*  ei    = d_in[1];
    const float* eattr = (const float*)d_in[2];

    const float* Wl[3]   = {(const float*)d_in[3],  (const float*)d_in[10], (const float*)d_in[17]};
    const float* bl[3]   = {(const float*)d_in[4],  (const float*)d_in[11], (const float*)d_in[18]};
    const float* Wr[3]   = {(const float*)d_in[5],  (const float*)d_in[12], (const float*)d_in[19]};
    const float* br[3]   = {(const float*)d_in[6],  (const float*)d_in[13], (const float*)d_in[20]};
    const float* We[3]   = {(const float*)d_in[7],  (const float*)d_in[14], (const float*)d_in[21]};
    const float* att[3]  = {(const float*)d_in[8],  (const float*)d_in[15], (const float*)d_in[22]};
    const float* bias[3] = {(const float*)d_in[9],  (const float*)d_in[16], (const float*)d_in[23]};
    const float* prelu_w = (const float*)d_in[24];

    int n = in_sizes[0] / 256;  // 50000
    int e = in_sizes[2];        // 800000

    float *xl, *xr, *h1, *h2;
    __nv_bfloat16 *ah, *al, *bhl, *bll, *bhr, *blr;
    cudaGetSymbolAddress((void**)&xl, g_xl);
    cudaGetSymbolAddress((void**)&xr, g_xr);
    cudaGetSymbolAddress((void**)&h1, g_h1);
    cudaGetSymbolAddress((void**)&h2, g_h2);
    cudaGetSymbolAddress((void**)&ah, g_ah);
    cudaGetSymbolAddress((void**)&al, g_al);
    cudaGetSymbolAddress((void**)&bhl, g_bhl);
    cudaGetSymbolAddress((void**)&bll, g_bll);
    cudaGetSymbolAddress((void**)&bhr, g_bhr);
    cudaGetSymbolAddress((void**)&blr, g_blr);

    cudaFuncSetAttribute(gemm_mma_kernel,
                         cudaFuncAttributeMaxDynamicSharedMemorySize, GEMM_SMEM);

    // --- CSR build ---
    detect_kernel<<<1, 32>>>((const int*)ei, e);
    init_kernel<<<(n + 255) / 256, 256>>>(n);
    count_kernel<<<(e + 255) / 256, 256>>>(ei, eattr, e, n);
    loopattr_kernel<<<(n + 255) / 256, 256>>>(n);
    scan_kernel<<<1, 1024>>>(n);
    fill_kernel<<<(e + 255) / 256, 256>>>(ei, eattr, e, n);
    fill_loop_kernel<<<(n + 255) / 256, 256>>>(n);

    int mtiles = (n + 127) / 128;
    dim3 ggrid(mtiles, 2, 2);
    int edge_blocks = (n * 32 + 255) / 256;

    // --- Layer 1 (K=256) ---
    conv_a_kernel<<<(n * 256 + 255) / 256, 256>>>(x, ah, al, n * 256);
    conv_w_kernel<<<(256 * 256 + 255) / 256, 256>>>(Wl[0], bhl, bll, 256);
    conv_w_kernel<<<(256 * 256 + 255) / 256, 256>>>(Wr[0], bhr, blr, 256);
    gemm_mma_kernel<<<ggrid, 256, GEMM_SMEM>>>(ah, al, bhl, bll, bl[0], xl,
                                               bhr, blr, br[0], xr, n, 256);
    gat_edge_kernel<<<edge_blocks, 256>>>(xl, xr, We[0], att[0], bias[0],
                                          prelu_w, h1, n, 0);
    // --- Layer 2 (K=64) ---
    conv_a_kernel<<<(n * 64 + 255) / 256, 256>>>(h1, ah, al, n * 64);
    conv_w_kernel<<<(256 * 64 + 255) / 256, 256>>>(Wl[1], bhl, bll, 64);
    conv_w_kernel<<<(256 * 64 + 255) / 256, 256>>>(Wr[1], bhr, blr, 64);
    gemm_mma_kernel<<<ggrid, 256, GEMM_SMEM>>>(ah, al, bhl, bll, bl[1], xl,
                                               bhr, blr, br[1], xr, n, 64);
    gat_edge_kernel<<<edge_blocks, 256>>>(xl, xr, We[1], att[1], bias[1],
                                          prelu_w, h2, n, 0);
    // --- Layer 3 (K=64) + PReLU ---
    conv_a_kernel<<<(n * 64 + 255) / 256, 256>>>(h2, ah, al, n * 64);
    conv_w_kernel<<<(256 * 64 + 255) / 256, 256>>>(Wl[2], bhl, bll, 64);
    conv_w_kernel<<<(256 * 64 + 255) / 256, 256>>>(Wr[2], bhr, blr, 64);
    gemm_mma_kernel<<<ggrid, 256, GEMM_SMEM>>>(ah, al, bhl, bll, bl[2], xl,
                                               bhr, blr, br[2], xr, n, 64);
    gat_edge_kernel<<<edge_blocks, 256>>>(xl, xr, We[2], att[2], bias[2],
                                          prelu_w, (float*)d_out, n, 1);
}

// round 7
// speedup vs baseline: 1.7961x; 1.1284x over previous
#include <cuda_runtime.h>
#include <cuda_bf16.h>
#include <math.h>
#include <stdint.h>

// ---------------------------------------------------------------------------
// Problem constants: N=50000, E=800000, IN=256, C=64, H=4
// ---------------------------------------------------------------------------
#define NMAX   50000
#define EMAX   800000
#define E2MAX  (EMAX + NMAX)
#define HC     256          // H*C
#define CCH    64           // C
#define NEG_SLOPE 0.2f

// ---------------------------------------------------------------------------
// Scratch
// ---------------------------------------------------------------------------
__device__ __align__(256) float g_xl[(size_t)NMAX * HC];
__device__ __align__(256) float g_xr[(size_t)NMAX * HC];
__device__ __align__(256) __nv_bfloat16 g_ah[(size_t)NMAX * HC];
__device__ __align__(256) __nv_bfloat16 g_al[(size_t)NMAX * HC];
__device__ __align__(256) __nv_bfloat16 g_bhl[256 * 256];
__device__ __align__(256) __nv_bfloat16 g_bll[256 * 256];
__device__ __align__(256) __nv_bfloat16 g_bhr[256 * 256];
__device__ __align__(256) __nv_bfloat16 g_blr[256 * 256];
__device__ __align__(256) int   g_cnt[NMAX];
__device__ __align__(256) float g_sumattr[NMAX];
__device__ __align__(256) float g_loopattr[NMAX];
__device__ __align__(256) int   g_off[NMAX + 2];
__device__ __align__(256) int   g_cursor[NMAX];
__device__ __align__(256) int   g_csr_src[E2MAX];
__device__ __align__(256) float g_csr_attr[E2MAX];
__device__ int g_is64;

// ---------------------------------------------------------------------------
// edge_index dtype probe + CSR build
// ---------------------------------------------------------------------------
__device__ __forceinline__ int load_idx(const void* ei, int is64, size_t pos) {
    if (is64) return (int)((const long long*)ei)[pos];
    return ((const int*)ei)[pos];
}
__global__ void detect_kernel(const int* ei32, int e) {
    if (threadIdx.x != 0 || blockIdx.x != 0) return;
    int nz = 0;
    int lim = (e < 64) ? e : 64;
    for (int i = 0; i < lim; ++i) nz |= ei32[2 * i + 1];
    g_is64 = (nz == 0) ? 1 : 0;
}
__global__ void init_kernel(int n) {
    int i = blockIdx.x * blockDim.x + threadIdx.x;
    if (i < n) { g_cnt[i] = 0; g_sumattr[i] = 0.f; }
}
__global__ void count_kernel(const void* __restrict__ ei,
                             const float* __restrict__ eattr, int e, int n) {
    int i = blockIdx.x * blockDim.x + threadIdx.x;
    if (i >= e) return;
    int is64 = g_is64;
    int d = load_idx(ei, is64, (size_t)e + i);
    if ((unsigned)d >= (unsigned)n) return;
    atomicAdd(&g_cnt[d], 1);
    atomicAdd(&g_sumattr[d], eattr[i]);
}
__global__ void loopattr_kernel(int n) {
    int i = blockIdx.x * blockDim.x + threadIdx.x;
    if (i >= n) return;
    int c = g_cnt[i];
    g_loopattr[i] = g_sumattr[i] / (float)(c > 1 ? c : 1);
}
__global__ void scan_kernel(int n) {
    __shared__ int sm[1024];
    __shared__ int s_carry;
    int tid = threadIdx.x;
    if (tid == 0) s_carry = 0;
    __syncthreads();
    for (int base = 0; base < n; base += 1024) {
        int i = base + tid;
        int v = (i < n) ? (g_cnt[i] + 1) : 0;
        sm[tid] = v;
        __syncthreads();
        for (int d = 1; d < 1024; d <<= 1) {
            int t = (tid >= d) ? sm[tid - d] : 0;
            __syncthreads();
            sm[tid] += t;
            __syncthreads();
        }
        int incl = sm[tid];
        int excl = incl - v + s_carry;
        if (i < n) { g_off[i] = excl; g_cursor[i] = excl; }
        __syncthreads();
        if (tid == 1023) s_carry += incl;
        __syncthreads();
    }
    if (tid == 0) g_off[n] = s_carry;
}
__global__ void fill_kernel(const void* __restrict__ ei,
                            const float* __restrict__ eattr, int e, int n) {
    int i = blockIdx.x * blockDim.x + threadIdx.x;
    if (i >= e) return;
    int is64 = g_is64;
    int s = load_idx(ei, is64, (size_t)i);
    int d = load_idx(ei, is64, (size_t)e + i);
    if ((unsigned)d >= (unsigned)n || (unsigned)s >= (unsigned)n) return;
    int pos = atomicAdd(&g_cursor[d], 1);
    g_csr_src[pos]  = s;
    g_csr_attr[pos] = eattr[i];
}
__global__ void fill_loop_kernel(int n) {
    int i = blockIdx.x * blockDim.x + threadIdx.x;
    if (i >= n) return;
    int pos = atomicAdd(&g_cursor[i], 1);
    g_csr_src[pos]  = i;
    g_csr_attr[pos] = g_loopattr[i];
}

// ---------------------------------------------------------------------------
// fp32 -> bf16 hi/lo split (layer-1 activations) and transposed hi/lo weights
// ---------------------------------------------------------------------------
__global__ void conv_a_kernel(const float* __restrict__ A,
                              __nv_bfloat16* __restrict__ Ah,
                              __nv_bfloat16* __restrict__ Al, int total) {
    int i = blockIdx.x * blockDim.x + threadIdx.x;
    if (i >= total) return;
    float v = A[i];
    __nv_bfloat16 h = __float2bfloat16(v);
    float r = v - __bfloat162float(h);
    Ah[i] = h;
    Al[i] = __float2bfloat16(r);
}
// W [K,256] row-major -> Bt [256,K] (K-major rows), hi/lo split
__global__ void conv_w_kernel(const float* __restrict__ W,
                              __nv_bfloat16* __restrict__ Bh,
                              __nv_bfloat16* __restrict__ Bl, int K) {
    int i = blockIdx.x * blockDim.x + threadIdx.x;
    if (i >= 256 * K) return;
    int nrow = i / K;
    int k = i - nrow * K;
    float v = W[(size_t)k * 256 + nrow];
    __nv_bfloat16 h = __float2bfloat16(v);
    float r = v - __bfloat162float(h);
    Bh[(size_t)nrow * K + k] = h;
    Bl[(size_t)nrow * K + k] = __float2bfloat16(r);
}

// ---------------------------------------------------------------------------
// HMMA GEMM (base-ISA mma.sync, bf16 3-split):
//   C[M,256] = A[M,K] @ W[K,256] + bias
// CTA tile 128x128, 8 warps (4m x 2n), warp tile 32x64, K-chunk 64.
// ---------------------------------------------------------------------------
#define KC 64
#define PADW 36
#define ROWB (PADW * 4)
#define SM_AH 0
#define SM_AL (128 * ROWB)
#define SM_BH (2 * 128 * ROWB)
#define SM_BL (3 * 128 * ROWB)
#define GEMM_SMEM (4 * 128 * ROWB)

__device__ __forceinline__ void mma_bf16(float* c, const uint32_t* a,
                                         uint32_t b0, uint32_t b1) {
    asm volatile(
        "mma.sync.aligned.m16n8k16.row.col.f32.bf16.bf16.f32 "
        "{%0,%1,%2,%3}, {%4,%5,%6,%7}, {%8,%9}, {%0,%1,%2,%3};"
        : "+f"(c[0]), "+f"(c[1]), "+f"(c[2]), "+f"(c[3])
        : "r"(a[0]), "r"(a[1]), "r"(a[2]), "r"(a[3]), "r"(b0), "r"(b1));
}

__global__ __launch_bounds__(256)
void gemm_mma_kernel(const __nv_bfloat16* __restrict__ Ah,
                     const __nv_bfloat16* __restrict__ Al,
                     const __nv_bfloat16* __restrict__ Bh0,
                     const __nv_bfloat16* __restrict__ Bl0,
                     const float* __restrict__ bias0, float* __restrict__ C0,
                     const __nv_bfloat16* __restrict__ Bh1,
                     const __nv_bfloat16* __restrict__ Bl1,
                     const float* __restrict__ bias1, float* __restrict__ C1,
                     int M, int K) {
    extern __shared__ char dsm[];

    const __nv_bfloat16* Bh = blockIdx.y ? Bh1 : Bh0;
    const __nv_bfloat16* Bl = blockIdx.y ? Bl1 : Bl0;
    const float* bias = blockIdx.y ? bias1 : bias0;
    float* C = blockIdx.y ? C1 : C0;
    int m0 = blockIdx.x * 128;
    int n0 = blockIdx.z * 128;

    int tid = threadIdx.x;
    int wid = tid >> 5, lane = tid & 31;
    int warpM = wid & 3, warpN = wid >> 2;
    int r = lane >> 2, q = lane & 3;

    const uint32_t* AHw = (const uint32_t*)(dsm + SM_AH);
    const uint32_t* ALw = (const uint32_t*)(dsm + SM_AL);
    const uint32_t* BHw = (const uint32_t*)(dsm + SM_BH);
    const uint32_t* BLw = (const uint32_t*)(dsm + SM_BL);

    float acc[2][8][4] = {};

    int lrow = tid >> 1;
    int lseg = tid & 1;

    int nchunks = K / KC;
    for (int t = 0; t < nchunks; ++t) {
        int k0 = t * KC;
        {
            int m = m0 + lrow;
            bool v = m < M;
            size_t ga = (size_t)m * K + k0 + lseg * 32;
            const uint4* sa_h = (const uint4*)(Ah + ga);
            const uint4* sa_l = (const uint4*)(Al + ga);
            size_t gb = (size_t)(n0 + lrow) * K + k0 + lseg * 32;
            const uint4* sb_h = (const uint4*)(Bh + gb);
            const uint4* sb_l = (const uint4*)(Bl + gb);
            uint32_t doff = lrow * ROWB + lseg * 64;
            uint4* da_h = (uint4*)(dsm + SM_AH + doff);
            uint4* da_l = (uint4*)(dsm + SM_AL + doff);
            uint4* db_h = (uint4*)(dsm + SM_BH + doff);
            uint4* db_l = (uint4*)(dsm + SM_BL + doff);
            uint4 z = make_uint4(0, 0, 0, 0);
            #pragma unroll
            for (int j = 0; j < 4; ++j) {
                da_h[j] = v ? sa_h[j] : z;
                da_l[j] = v ? sa_l[j] : z;
                db_h[j] = sb_h[j];
                db_l[j] = sb_l[j];
            }
        }
        __syncthreads();

        #pragma unroll
        for (int ks = 0; ks < KC / 16; ++ks) {
            int kw = ks * 8;
            uint32_t ah[2][4], al[2][4];
            #pragma unroll
            for (int mi = 0; mi < 2; ++mi) {
                int rb  = (warpM * 32 + mi * 16 + r) * PADW + kw + q;
                int rb8 = rb + 8 * PADW;
                ah[mi][0] = AHw[rb];     ah[mi][1] = AHw[rb8];
                ah[mi][2] = AHw[rb + 4]; ah[mi][3] = AHw[rb8 + 4];
                al[mi][0] = ALw[rb];     al[mi][1] = ALw[rb8];
                al[mi][2] = ALw[rb + 4]; al[mi][3] = ALw[rb8 + 4];
            }
            #pragma unroll
            for (int ni = 0; ni < 8; ++ni) {
                int nb = (warpN * 64 + ni * 8 + r) * PADW + kw + q;
                uint32_t bh0 = BHw[nb], bh1 = BHw[nb + 4];
                uint32_t bl0 = BLw[nb], bl1 = BLw[nb + 4];
                #pragma unroll
                for (int mi = 0; mi < 2; ++mi) {
                    mma_bf16(acc[mi][ni], ah[mi], bh0, bh1);
                    mma_bf16(acc[mi][ni], ah[mi], bl0, bl1);
                    mma_bf16(acc[mi][ni], al[mi], bh0, bh1);
                }
            }
        }
        __syncthreads();
    }

    #pragma unroll
    for (int ni = 0; ni < 8; ++ni) {
        int gn = n0 + warpN * 64 + ni * 8 + q * 2;
        float bx = bias[gn], by = bias[gn + 1];
        #pragma unroll
        for (int mi = 0; mi < 2; ++mi) {
            int gm = m0 + warpM * 32 + mi * 16 + r;
            if (gm < M) {
                float2 o0 = make_float2(acc[mi][ni][0] + bx, acc[mi][ni][1] + by);
                *(float2*)(C + (size_t)gm * 256 + gn) = o0;
            }
            if (gm + 8 < M) {
                float2 o1 = make_float2(acc[mi][ni][2] + bx, acc[mi][ni][3] + by);
                *(float2*)(C + (size_t)(gm + 8) * 256 + gn) = o1;
            }
        }
    }
}

// ---------------------------------------------------------------------------
// Fused GATv2 edge phase — no-max softmax (scores provably tiny; every node
// has a self loop), unrolled x2 for MLP. One warp per destination node.
// Output: if out != nullptr -> fp32 (+optional PReLU). Else -> bf16 hi/lo
// split into ah/al (feeds next layer's GEMM directly).
// ---------------------------------------------------------------------------
__global__ void gat_edge_kernel(const float* __restrict__ xl,
                                const float* __restrict__ xr,
                                const float* __restrict__ We,
                                const float* __restrict__ att,
                                const float* __restrict__ bias,
                                const float* __restrict__ prelu_w,
                                float* __restrict__ out,
                                __nv_bfloat16* __restrict__ oh,
                                __nv_bfloat16* __restrict__ ol,
                                int n, int use_prelu) {
    int warp = (blockIdx.x * blockDim.x + threadIdx.x) >> 5;
    if (warp >= n) return;
    int lane = threadIdx.x & 31;
    int sub  = lane & 7;
    int base = (lane >> 3) * CCH + sub * 8;

    float we[8], at[8], xrv[8];
    {
        float4 a = *(const float4*)(We + base);
        float4 b = *(const float4*)(We + base + 4);
        we[0]=a.x; we[1]=a.y; we[2]=a.z; we[3]=a.w;
        we[4]=b.x; we[5]=b.y; we[6]=b.z; we[7]=b.w;
        a = *(const float4*)(att + base);
        b = *(const float4*)(att + base + 4);
        at[0]=a.x; at[1]=a.y; at[2]=a.z; at[3]=a.w;
        at[4]=b.x; at[5]=b.y; at[6]=b.z; at[7]=b.w;
        const float* xp = xr + (size_t)warp * HC + base;
        a = *(const float4*)xp;
        b = *(const float4*)(xp + 4);
        xrv[0]=a.x; xrv[1]=a.y; xrv[2]=a.z; xrv[3]=a.w;
        xrv[4]=b.x; xrv[5]=b.y; xrv[6]=b.z; xrv[7]=b.w;
    }

    int p0 = g_off[warp], p1 = g_off[warp + 1];

    float den = 0.f;
    float acc[8] = {};

    int p = p0;
    for (; p + 1 < p1; p += 2) {
        int s0   = g_csr_src[p];
        int s1   = g_csr_src[p + 1];
        float a0 = g_csr_attr[p];
        float a1 = g_csr_attr[p + 1];
        const float* xp0 = xl + (size_t)s0 * HC + base;
        const float* xp1 = xl + (size_t)s1 * HC + base;
        float4 u0 = *(const float4*)xp0;
        float4 u1 = *(const float4*)(xp0 + 4);
        float4 w0 = *(const float4*)xp1;
        float4 w1 = *(const float4*)(xp1 + 4);
        float xv0[8] = {u0.x, u0.y, u0.z, u0.w, u1.x, u1.y, u1.z, u1.w};
        float xv1[8] = {w0.x, w0.y, w0.z, w0.w, w1.x, w1.y, w1.z, w1.w};
        float sc0 = 0.f, sc1 = 0.f;
        #pragma unroll
        for (int j = 0; j < 8; ++j) {
            float m0_ = xv0[j] + xrv[j] + a0 * we[j];
            float m1_ = xv1[j] + xrv[j] + a1 * we[j];
            m0_ = (m0_ >= 0.f) ? m0_ : NEG_SLOPE * m0_;
            m1_ = (m1_ >= 0.f) ? m1_ : NEG_SLOPE * m1_;
            sc0 += m0_ * at[j];
            sc1 += m1_ * at[j];
        }
        sc0 += __shfl_xor_sync(0xffffffffu, sc0, 1);
        sc1 += __shfl_xor_sync(0xffffffffu, sc1, 1);
        sc0 += __shfl_xor_sync(0xffffffffu, sc0, 2);
        sc1 += __shfl_xor_sync(0xffffffffu, sc1, 2);
        sc0 += __shfl_xor_sync(0xffffffffu, sc0, 4);
        sc1 += __shfl_xor_sync(0xffffffffu, sc1, 4);
        float ex0 = __expf(sc0);
        float ex1 = __expf(sc1);
        den += ex0 + ex1;
        #pragma unroll
        for (int j = 0; j < 8; ++j)
            acc[j] += ex0 * xv0[j] + ex1 * xv1[j];
    }
    if (p < p1) {
        int s   = g_csr_src[p];
        float a = g_csr_attr[p];
        const float* xp = xl + (size_t)s * HC + base;
        float4 v0 = *(const float4*)xp;
        float4 v1 = *(const float4*)(xp + 4);
        float xv[8] = {v0.x, v0.y, v0.z, v0.w, v1.x, v1.y, v1.z, v1.w};
        float sc = 0.f;
        #pragma unroll
        for (int j = 0; j < 8; ++j) {
            float m = xv[j] + xrv[j] + a * we[j];
            m = (m >= 0.f) ? m : NEG_SLOPE * m;
            sc += m * at[j];
        }
        sc += __shfl_xor_sync(0xffffffffu, sc, 1);
        sc += __shfl_xor_sync(0xffffffffu, sc, 2);
        sc += __shfl_xor_sync(0xffffffffu, sc, 4);
        float ex = __expf(sc);
        den += ex;
        #pragma unroll
        for (int j = 0; j < 8; ++j) acc[j] += ex * xv[j];
    }

    float invd = 1.f / (den + 1e-16f);
    float res[8];
    #pragma unroll
    for (int j = 0; j < 8; ++j) {
        float v = acc[j] * invd;
        v += __shfl_xor_sync(0xffffffffu, v, 8);
        v += __shfl_xor_sync(0xffffffffu, v, 16);
        res[j] = v * 0.25f;
    }
    if (lane < 8) {
        if (out) {
            #pragma unroll
            for (int j = 0; j < 8; ++j) {
                int c = sub * 8 + j;
                float o = res[j] + bias[c];
                if (use_prelu) o = (o >= 0.f) ? o : prelu_w[c] * o;
                out[(size_t)warp * CCH + c] = o;
            }
        } else {
            // bf16 hi/lo split for next layer's GEMM A operand
            __nv_bfloat16 hbuf[8], lbuf[8];
            #pragma unroll
            for (int j = 0; j < 8; ++j) {
                int c = sub * 8 + j;
                float o = res[j] + bias[c];
                __nv_bfloat16 h = __float2bfloat16(o);
                hbuf[j] = h;
                lbuf[j] = __float2bfloat16(o - __bfloat162float(h));
            }
            *(uint4*)(oh + (size_t)warp * CCH + sub * 8) = *(const uint4*)hbuf;
            *(uint4*)(ol + (size_t)warp * CCH + sub * 8) = *(const uint4*)lbuf;
        }
    }
}

// ---------------------------------------------------------------------------
// Host launch
// ---------------------------------------------------------------------------
extern "C" void kernel_launch(void* const* d_in, const int* in_sizes, int n_in,
                              void* d_out, int out_size) {
    const float* x     = (const float*)d_in[0];
    const void*  ei    = d_in[1];
    const float* eattr = (const float*)d_in[2];

    const float* Wl[3]   = {(const float*)d_in[3],  (const float*)d_in[10], (const float*)d_in[17]};
    const float* bl[3]   = {(const float*)d_in[4],  (const float*)d_in[11], (const float*)d_in[18]};
    const float* Wr[3]   = {(const float*)d_in[5],  (const float*)d_in[12], (const float*)d_in[19]};
    const float* br[3]   = {(const float*)d_in[6],  (const float*)d_in[13], (const float*)d_in[20]};
    const float* We[3]   = {(const float*)d_in[7],  (const float*)d_in[14], (const float*)d_in[21]};
    const float* att[3]  = {(const float*)d_in[8],  (const float*)d_in[15], (const float*)d_in[22]};
    const float* bias[3] = {(const float*)d_in[9],  (const float*)d_in[16], (const float*)d_in[23]};
    const float* prelu_w = (const float*)d_in[24];

    int n = in_sizes[0] / 256;  // 50000
    int e = in_sizes[2];        // 800000

    float *xl, *xr;
    __nv_bfloat16 *ah, *al, *bhl, *bll, *bhr, *blr;
    cudaGetSymbolAddress((void**)&xl, g_xl);
    cudaGetSymbolAddress((void**)&xr, g_xr);
    cudaGetSymbolAddress((void**)&ah, g_ah);
    cudaGetSymbolAddress((void**)&al, g_al);
    cudaGetSymbolAddress((void**)&bhl, g_bhl);
    cudaGetSymbolAddress((void**)&bll, g_bll);
    cudaGetSymbolAddress((void**)&bhr, g_bhr);
    cudaGetSymbolAddress((void**)&blr, g_blr);

    cudaFuncSetAttribute(gemm_mma_kernel,
                         cudaFuncAttributeMaxDynamicSharedMemorySize, GEMM_SMEM);

    // --- CSR build ---
    detect_kernel<<<1, 32>>>((const int*)ei, e);
    init_kernel<<<(n + 255) / 256, 256>>>(n);
    count_kernel<<<(e + 255) / 256, 256>>>(ei, eattr, e, n);
    loopattr_kernel<<<(n + 255) / 256, 256>>>(n);
    scan_kernel<<<1, 1024>>>(n);
    fill_kernel<<<(e + 255) / 256, 256>>>(ei, eattr, e, n);
    fill_loop_kernel<<<(n + 255) / 256, 256>>>(n);

    int mtiles = (n + 127) / 128;
    dim3 ggrid(mtiles, 2, 2);
    int edge_blocks = (n * 32 + 255) / 256;

    // --- Layer 1 (K=256) ---
    conv_a_kernel<<<(n * 256 + 255) / 256, 256>>>(x, ah, al, n * 256);
    conv_w_kernel<<<(256 * 256 + 255) / 256, 256>>>(Wl[0], bhl, bll, 256);
    conv_w_kernel<<<(256 * 256 + 255) / 256, 256>>>(Wr[0], bhr, blr, 256);
    gemm_mma_kernel<<<ggrid, 256, GEMM_SMEM>>>(ah, al, bhl, bll, bl[0], xl,
                                               bhr, blr, br[0], xr, n, 256);
    // edge -> bf16 split directly into ah/al (64 cols)
    gat_edge_kernel<<<edge_blocks, 256>>>(xl, xr, We[0], att[0], bias[0],
                                          prelu_w, nullptr, ah, al, n, 0);
    // --- Layer 2 (K=64) ---
    conv_w_kernel<<<(256 * 64 + 255) / 256, 256>>>(Wl[1], bhl, bll, 64);
    conv_w_kernel<<<(256 * 64 + 255) / 256, 256>>>(Wr[1], bhr, blr, 64);
    gemm_mma_kernel<<<ggrid, 256, GEMM_SMEM>>>(ah, al, bhl, bll, bl[1], xl,
                                               bhr, blr, br[1], xr, n, 64);
    gat_edge_kernel<<<edge_blocks, 256>>>(xl, xr, We[1], att[1], bias[1],
                                          prelu_w, nullptr, ah, al, n, 0);
    // --- Layer 3 (K=64) + PReLU ---
    conv_w_kernel<<<(256 * 64 + 255) / 256, 256>>>(Wl[2], bhl, bll, 64);
    conv_w_kernel<<<(256 * 64 + 255) / 256, 256>>>(Wr[2], bhr, blr, 64);
    gemm_mma_kernel<<<ggrid, 256, GEMM_SMEM>>>(ah, al, bhl, bll, bl[2], xl,
                                               bhr, blr, br[2], xr, n, 64);
    gat_edge_kernel<<<edge_blocks, 256>>>(xl, xr, We[2], att[2], bias[2],
                                          prelu_w, (float*)d_out, nullptr, nullptr, n, 1);
}